// round 4
// baseline (speedup 1.0000x reference)
#include <cuda_runtime.h>
#include <math.h>

#define NNODES 10000
#define NHID   128
#define UC     1032   // U row: xh(512) | res(512) | a_src(4) | a_dst(4)
#define NB     1032
#define EMAX   160000

// ---------------- scratch (device globals; no allocation allowed) ----------
__device__ float g_X0[NNODES * NHID];
__device__ float g_X1[NNODES * NHID];
__device__ float g_U [NNODES * UC];
__device__ float g_B [NB * NHID];     // fused weights [1032,128]
__device__ float g_bias[NB];
__device__ int   g_deg[NNODES];
__device__ int   g_cur[NNODES];
__device__ int   g_off[NNODES + 1];
__device__ int   g_csr[EMAX];
__device__ int   g_is64;

// ---------------- helpers ---------------------------------------------------
__device__ __forceinline__ float lrelu(float x) { return x > 0.f ? x : 0.2f * x; }
__device__ __forceinline__ float eluf (float x) { return x > 0.f ? x : (expf(x) - 1.f); }

__device__ __forceinline__ unsigned long long pk2(float lo, float hi) {
    unsigned long long r;
    asm("mov.b64 %0, {%1, %2};" : "=l"(r) : "f"(lo), "f"(hi));
    return r;
}
__device__ __forceinline__ void fma2(unsigned long long& d,
                                     unsigned long long a, unsigned long long b) {
    asm("fma.rn.f32x2 %0, %1, %2, %3;" : "=l"(d) : "l"(a), "l"(b), "l"(d));
}
__device__ __forceinline__ void upk2(float& lo, float& hi, unsigned long long v) {
    asm("mov.b64 {%0, %1}, %2;" : "=f"(lo), "=f"(hi) : "l"(v));
}

__device__ __forceinline__ const float* sel_ptr(const float* ext, int sel) {
    if (sel == 1) return g_X0;
    if (sel == 2) return g_X1;
    if (sel == 3) return g_U;
    if (sel == 4) return g_B;
    if (sel == 5) return g_bias;
    return ext;
}

__device__ __forceinline__ int edge_at(const void* ei, int idx, int is64) {
    if (is64) return (int)((const long long*)ei)[idx];
    return ((const int*)ei)[idx];
}

// ---------------- init: zero deg/cur (all blocks) + dtype sniff (block 0) ---
__global__ void init_kernel(const void* ei) {
    int i = blockIdx.x * blockDim.x + threadIdx.x;
    if (i < NNODES) { g_deg[i] = 0; g_cur[i] = 0; }
    if (blockIdx.x == 0) {
        __shared__ int acc[256];
        int t = threadIdx.x;
        const unsigned* w = (const unsigned*)ei;
        unsigned o = 0;
        #pragma unroll
        for (int j = 0; j < 8; j++) o |= w[(t + j * 256) * 2 + 1];
        acc[t] = (int)(o != 0);
        __syncthreads();
        for (int s = 128; s > 0; s >>= 1) {
            if (t < s) acc[t] |= acc[t + s];
            __syncthreads();
        }
        if (t == 0) g_is64 = acc[0] ? 0 : 1;   // any nonzero odd word -> int32
    }
}

// ---------------- CSR build -------------------------------------------------
__global__ void count_kernel(const void* __restrict__ ei, int E) {
    int e = blockIdx.x * blockDim.x + threadIdx.x;
    if (e < E) atomicAdd(&g_deg[edge_at(ei, E + e, g_is64)], 1);
}

__global__ void scan_kernel(int n) {   // 1 block, 1024 threads, shuffle scan
    __shared__ int wsum[32];
    int t = threadIdx.x, lane = t & 31, w = t >> 5;
    const int chunk = 10;
    int base_i = t * chunk;
    int s = 0;
    #pragma unroll
    for (int i = 0; i < chunk; i++) {
        int idx = base_i + i;
        if (idx < n) s += g_deg[idx];
    }
    int v = s;
    #pragma unroll
    for (int o = 1; o < 32; o <<= 1) {
        int u = __shfl_up_sync(0xffffffffu, v, o);
        if (lane >= o) v += u;
    }
    if (lane == 31) wsum[w] = v;
    __syncthreads();
    if (w == 0) {
        int x = wsum[lane];
        #pragma unroll
        for (int o = 1; o < 32; o <<= 1) {
            int u = __shfl_up_sync(0xffffffffu, x, o);
            if (lane >= o) x += u;
        }
        wsum[lane] = x;
    }
    __syncthreads();
    int run = (w ? wsum[w - 1] : 0) + v - s;   // exclusive prefix
    #pragma unroll
    for (int i = 0; i < chunk; i++) {
        int idx = base_i + i;
        if (idx < n) { g_off[idx] = run; run += g_deg[idx]; }
    }
    if (t == 1023) g_off[n] = run;
}

__global__ void scatter_kernel(const void* __restrict__ ei, int E) {
    int e = blockIdx.x * blockDim.x + threadIdx.x;
    if (e < E) {
        int is64 = g_is64;
        int d = edge_at(ei, E + e, is64);
        int p = g_off[d] + atomicAdd(&g_cur[d], 1);
        g_csr[p] = edge_at(ei, e, is64);
    }
}

// ---------------- fused weight + bias build ---------------------------------
// rows 0..511: gat_w | 512..1023: res_w | 1024..1027: fold(att_src) | 1028..1031: fold(att_dst)
__global__ __launch_bounds__(128)
void build_b_kernel(const float* __restrict__ gat_w,
                    const float* __restrict__ res_w,
                    const float* __restrict__ att_src,
                    const float* __restrict__ att_dst,
                    const float* __restrict__ res_b)
{
    int r = blockIdx.x;
    int t = threadIdx.x;
    if (r < 512) {
        g_B[r * 128 + t] = gat_w[r * 128 + t];
        if (t == 0) g_bias[r] = 0.f;
    } else if (r < 1024) {
        g_B[r * 128 + t] = res_w[(r - 512) * 128 + t];
        if (t == 0) g_bias[r] = res_b[r - 512];
    } else {
        int h = (r - 1024) & 3;
        const float* att = (r < 1028) ? att_src : att_dst;
        float s = 0.f;
        for (int c = 0; c < 128; c++)
            s = fmaf(att[h * 128 + c], gat_w[(size_t)(h * 128 + c) * 128 + t], s);
        g_B[r * 128 + t] = s;
        if (t == 0) g_bias[r] = 0.f;
    }
}

// ---------------- GEMM: C[m,n] = sum_k A[m,k]*B[n,k] (+bias)(+relu) --------
// A row-major [M,K], B row-major [N,K]. BM=128, BN=128, BK=16, 256 threads,
// 8x8 thread tile with fma.rn.f32x2 packed accumulation, double-buffered smem.
__global__ __launch_bounds__(256)
void gemm_kernel(const float* __restrict__ Aext, int Asel,
                 const float* __restrict__ Bext, int Bsel,
                 const float* __restrict__ biasext, int bsel,
                 float* __restrict__ Cext, int Csel,
                 int M, int N, int K, int ldc, int relu)
{
    const float* A = sel_ptr(Aext, Asel);
    const float* B = sel_ptr(Bext, Bsel);
    const float* bias = sel_ptr(biasext, bsel);
    float* C = (Csel == 1) ? g_X0 : (Csel == 2) ? g_X1 : (Csel == 3) ? g_U : Cext;

    __shared__ float As[2][16][132];
    __shared__ float Bs[2][16][132];

    const int tid = threadIdx.x;
    const int bm = blockIdx.x * 128, bn = blockIdx.y * 128;
    const int tx = tid & 15, ty = tid >> 4;

    // loads: each tile 128x16 = 512 float4, 2 per thread
    const int r0 = tid >> 2;          // 0..63
    const int r1 = 64 + (tid >> 2);   // 64..127
    const int k4 = tid & 3;

    float4 pa0, pa1, pb0, pb1;
    const int nt = K >> 4;

    {   // prologue (kt = 0)
        int gm0 = bm + r0, gm1 = bm + r1, gn0 = bn + r0, gn1 = bn + r1;
        pa0 = (gm0 < M) ? *(const float4*)(A + (size_t)gm0 * K + k4 * 4) : make_float4(0, 0, 0, 0);
        pa1 = (gm1 < M) ? *(const float4*)(A + (size_t)gm1 * K + k4 * 4) : make_float4(0, 0, 0, 0);
        pb0 = (gn0 < N) ? *(const float4*)(B + (size_t)gn0 * K + k4 * 4) : make_float4(0, 0, 0, 0);
        pb1 = (gn1 < N) ? *(const float4*)(B + (size_t)gn1 * K + k4 * 4) : make_float4(0, 0, 0, 0);
        As[0][k4 * 4 + 0][r0] = pa0.x; As[0][k4 * 4 + 1][r0] = pa0.y;
        As[0][k4 * 4 + 2][r0] = pa0.z; As[0][k4 * 4 + 3][r0] = pa0.w;
        As[0][k4 * 4 + 0][r1] = pa1.x; As[0][k4 * 4 + 1][r1] = pa1.y;
        As[0][k4 * 4 + 2][r1] = pa1.z; As[0][k4 * 4 + 3][r1] = pa1.w;
        Bs[0][k4 * 4 + 0][r0] = pb0.x; Bs[0][k4 * 4 + 1][r0] = pb0.y;
        Bs[0][k4 * 4 + 2][r0] = pb0.z; Bs[0][k4 * 4 + 3][r0] = pb0.w;
        Bs[0][k4 * 4 + 0][r1] = pb1.x; Bs[0][k4 * 4 + 1][r1] = pb1.y;
        Bs[0][k4 * 4 + 2][r1] = pb1.z; Bs[0][k4 * 4 + 3][r1] = pb1.w;
    }
    __syncthreads();

    unsigned long long acc[8][4];
    const unsigned long long z = pk2(0.f, 0.f);
    #pragma unroll
    for (int i = 0; i < 8; i++)
        #pragma unroll
        for (int j = 0; j < 4; j++) acc[i][j] = z;

    for (int t = 0; t < nt; t++) {
        int cur = t & 1;
        if (t + 1 < nt) {
            int kt = (t + 1) << 4;
            int gm0 = bm + r0, gm1 = bm + r1, gn0 = bn + r0, gn1 = bn + r1;
            pa0 = (gm0 < M) ? *(const float4*)(A + (size_t)gm0 * K + kt + k4 * 4) : make_float4(0, 0, 0, 0);
            pa1 = (gm1 < M) ? *(const float4*)(A + (size_t)gm1 * K + kt + k4 * 4) : make_float4(0, 0, 0, 0);
            pb0 = (gn0 < N) ? *(const float4*)(B + (size_t)gn0 * K + kt + k4 * 4) : make_float4(0, 0, 0, 0);
            pb1 = (gn1 < N) ? *(const float4*)(B + (size_t)gn1 * K + kt + k4 * 4) : make_float4(0, 0, 0, 0);
        }
        #pragma unroll
        for (int k = 0; k < 16; k++) {
            float4 av0 = *(const float4*)&As[cur][k][ty * 8];
            float4 av1 = *(const float4*)&As[cur][k][ty * 8 + 4];
            float4 bv0 = *(const float4*)&Bs[cur][k][tx * 8];
            float4 bv1 = *(const float4*)&Bs[cur][k][tx * 8 + 4];
            unsigned long long bp[4] = {
                pk2(bv0.x, bv0.y), pk2(bv0.z, bv0.w),
                pk2(bv1.x, bv1.y), pk2(bv1.z, bv1.w)
            };
            float a[8] = {av0.x, av0.y, av0.z, av0.w, av1.x, av1.y, av1.z, av1.w};
            #pragma unroll
            for (int i = 0; i < 8; i++) {
                unsigned long long ad = pk2(a[i], a[i]);
                fma2(acc[i][0], ad, bp[0]);
                fma2(acc[i][1], ad, bp[1]);
                fma2(acc[i][2], ad, bp[2]);
                fma2(acc[i][3], ad, bp[3]);
            }
        }
        if (t + 1 < nt) {
            int nxt = cur ^ 1;
            As[nxt][k4 * 4 + 0][r0] = pa0.x; As[nxt][k4 * 4 + 1][r0] = pa0.y;
            As[nxt][k4 * 4 + 2][r0] = pa0.z; As[nxt][k4 * 4 + 3][r0] = pa0.w;
            As[nxt][k4 * 4 + 0][r1] = pa1.x; As[nxt][k4 * 4 + 1][r1] = pa1.y;
            As[nxt][k4 * 4 + 2][r1] = pa1.z; As[nxt][k4 * 4 + 3][r1] = pa1.w;
            Bs[nxt][k4 * 4 + 0][r0] = pb0.x; Bs[nxt][k4 * 4 + 1][r0] = pb0.y;
            Bs[nxt][k4 * 4 + 2][r0] = pb0.z; Bs[nxt][k4 * 4 + 3][r0] = pb0.w;
            Bs[nxt][k4 * 4 + 0][r1] = pb1.x; Bs[nxt][k4 * 4 + 1][r1] = pb1.y;
            Bs[nxt][k4 * 4 + 2][r1] = pb1.z; Bs[nxt][k4 * 4 + 3][r1] = pb1.w;
            __syncthreads();
        }
    }

    #pragma unroll
    for (int i = 0; i < 8; i++) {
        int gm = bm + ty * 8 + i;
        if (gm >= M) continue;
        float v[8];
        upk2(v[0], v[1], acc[i][0]);
        upk2(v[2], v[3], acc[i][1]);
        upk2(v[4], v[5], acc[i][2]);
        upk2(v[6], v[7], acc[i][3]);
        #pragma unroll
        for (int j = 0; j < 8; j++) {
            int gn = bn + tx * 8 + j;
            if (gn >= N) continue;
            float val = v[j];
            if (bias) val += bias[gn];
            if (relu) val = fmaxf(val, 0.f);
            C[(size_t)gm * ldc + gn] = val;
        }
    }
}

// ---------------- GAT aggregation + fused GraphCON epilogue ----------------
// one block per destination node, 128 threads; thread t owns flat channels
// 4t..4t+3 which all live in head h = t>>5.
__global__ __launch_bounds__(128)
void node_kernel(const float* __restrict__ gat_b, int out_sel)
{
    float* Xnew = (out_sel == 1) ? g_X0 : g_X1;
    const int d = blockIdx.x, t = threadIdx.x;
    const int h = t >> 5, lane = t & 31;

    const float* ud = g_U + (size_t)d * UC;
    const float adv = ud[1028 + h];
    const float ls = lrelu(ud[1024 + h] + adv);
    const int e0 = g_off[d], e1 = g_off[d + 1];

    // ---- warp-level max over incoming logits (+self) ----
    float mx = ls;
    for (int i = e0 + lane; i < e1; i += 32) {
        int s = g_csr[i];
        mx = fmaxf(mx, lrelu(g_U[(size_t)s * UC + 1024 + h] + adv));
    }
    #pragma unroll
    for (int o = 16; o > 0; o >>= 1)
        mx = fmaxf(mx, __shfl_xor_sync(0xffffffffu, mx, o));

    // ---- fused pass: unnormalized weighted aggregate + weight sum ----
    float ws = expf(ls - mx);
    float ssum = ws;
    float4 xd4 = ((const float4*)ud)[t];
    float4 acc = make_float4(ws * xd4.x, ws * xd4.y, ws * xd4.z, ws * xd4.w);

    int i = e0;
    for (; i + 2 <= e1; i += 2) {
        int s0 = g_csr[i], s1 = g_csr[i + 1];
        const float* u0 = g_U + (size_t)s0 * UC;
        const float* u1 = g_U + (size_t)s1 * UC;
        float a0 = u0[1024 + h], a1 = u1[1024 + h];
        float4 v0 = ((const float4*)u0)[t];
        float4 v1 = ((const float4*)u1)[t];
        float w0 = expf(lrelu(a0 + adv) - mx);
        float w1 = expf(lrelu(a1 + adv) - mx);
        acc.x = fmaf(w0, v0.x, acc.x); acc.y = fmaf(w0, v0.y, acc.y);
        acc.z = fmaf(w0, v0.z, acc.z); acc.w = fmaf(w0, v0.w, acc.w);
        acc.x = fmaf(w1, v1.x, acc.x); acc.y = fmaf(w1, v1.y, acc.y);
        acc.z = fmaf(w1, v1.z, acc.z); acc.w = fmaf(w1, v1.w, acc.w);
        ssum += w0 + w1;
    }
    if (i < e1) {
        int s0 = g_csr[i];
        const float* u0 = g_U + (size_t)s0 * UC;
        float w0 = expf(lrelu(u0[1024 + h] + adv) - mx);
        float4 v0 = ((const float4*)u0)[t];
        acc.x = fmaf(w0, v0.x, acc.x); acc.y = fmaf(w0, v0.y, acc.y);
        acc.z = fmaf(w0, v0.z, acc.z); acc.w = fmaf(w0, v0.w, acc.w);
        ssum += w0;
    }

    // ---- epilogue: v = conv/ssum + gat_b + res; z = mean over 4 flat elems
    float rcp = 1.f / ssum;
    float4 gb = ((const float4*)gat_b)[t];
    float4 rs = ((const float4*)(ud + 512))[t];
    float z = 0.25f * (eluf(fmaf(acc.x, rcp, gb.x + rs.x)) +
                       eluf(fmaf(acc.y, rcp, gb.y + rs.y)) +
                       eluf(fmaf(acc.z, rcp, gb.z + rs.z)) +
                       eluf(fmaf(acc.w, rcp, gb.w + rs.w)));
    Xnew[(size_t)d * NHID + t] = z;
}

// ---------------- host ------------------------------------------------------
extern "C" void kernel_launch(void* const* d_in, const int* in_sizes, int n_in,
                              void* d_out, int out_size)
{
    const float* x       = (const float*)d_in[0];
    const void*  ei      = d_in[1];
    const float* enc_w   = (const float*)d_in[2];
    const float* enc_b   = (const float*)d_in[3];
    const float* res_w   = (const float*)d_in[4];
    const float* res_b   = (const float*)d_in[5];
    const float* gat_w   = (const float*)d_in[6];
    const float* att_src = (const float*)d_in[7];
    const float* att_dst = (const float*)d_in[8];
    const float* gat_b   = (const float*)d_in[9];
    const float* dec_w   = (const float*)d_in[10];
    const float* dec_b   = (const float*)d_in[11];
    int E = in_sizes[1] / 2;

    // init (zero + dtype sniff) + CSR by destination
    init_kernel<<<(NNODES + 255) / 256, 256>>>(ei);
    count_kernel<<<(E + 255) / 256, 256>>>(ei, E);
    scan_kernel<<<1, 1024>>>(NNODES);
    scatter_kernel<<<(E + 255) / 256, 256>>>(ei, E);

    // fused weight + bias build (layer-invariant)
    build_b_kernel<<<NB, 128>>>(gat_w, res_w, att_src, att_dst, res_b);

    // encoder: X0 = relu(x @ enc_w^T + enc_b)
    gemm_kernel<<<dim3(79, 1), 256>>>(x, 0, enc_w, 0, enc_b, 0, nullptr, 1,
                                      NNODES, 128, 256, 128, 1);

    for (int layer = 0; layer < 2; layer++) {
        int in_sel  = (layer == 0) ? 1 : 2;
        int out_sel = (layer == 0) ? 2 : 1;
        // fused: U = Xc @ [gat_w; res_w; folds]^T + [0; res_b; 0]
        gemm_kernel<<<dim3(79, 9), 256>>>(nullptr, in_sel, nullptr, 4,
                                          nullptr, 5, nullptr, 3,
                                          NNODES, NB, 128, UC, 0);
        node_kernel<<<NNODES, 128>>>(gat_b, out_sel);
    }

    // decoder
    gemm_kernel<<<dim3(79, 1), 256>>>(nullptr, 1, dec_w, 0, dec_b, 0,
                                      (float*)d_out, 0,
                                      NNODES, 40, 128, 40, 0);
}

// round 5
// speedup vs baseline: 1.3311x; 1.3311x over previous
#include <cuda_runtime.h>
#include <math.h>

#define NNODES 10000
#define NHID   128
#define UC     1032   // U row: xh(512) | res(512) | a_src(4) | a_dst(4)
#define NB     1032
#define EMAX   160000

// ---------------- scratch (device globals; no allocation allowed) ----------
__device__ float g_X0[NNODES * NHID];
__device__ float g_X1[NNODES * NHID];
__device__ float g_U [NNODES * UC];
__device__ float g_B [NB * NHID];     // fused weights [1032,128]
__device__ float g_bias[NB];
__device__ int   g_deg[NNODES];
__device__ int   g_cur[NNODES];
__device__ int   g_off[NNODES + 1];
__device__ int   g_csr[EMAX];
__device__ int   g_is64;

// ---------------- helpers ---------------------------------------------------
__device__ __forceinline__ float lrelu(float x) { return x > 0.f ? x : 0.2f * x; }
__device__ __forceinline__ float eluf (float x) { return x > 0.f ? x : (expf(x) - 1.f); }

__device__ __forceinline__ unsigned long long pk2(float lo, float hi) {
    unsigned long long r;
    asm("mov.b64 %0, {%1, %2};" : "=l"(r) : "f"(lo), "f"(hi));
    return r;
}
__device__ __forceinline__ void fma2(unsigned long long& d,
                                     unsigned long long a, unsigned long long b) {
    asm("fma.rn.f32x2 %0, %1, %2, %3;" : "=l"(d) : "l"(a), "l"(b), "l"(d));
}
__device__ __forceinline__ void upk2(float& lo, float& hi, unsigned long long v) {
    asm("mov.b64 {%0, %1}, %2;" : "=f"(lo), "=f"(hi) : "l"(v));
}

__device__ __forceinline__ const float* sel_ptr(const float* ext, int sel) {
    if (sel == 1) return g_X0;
    if (sel == 2) return g_X1;
    if (sel == 3) return g_U;
    if (sel == 4) return g_B;
    if (sel == 5) return g_bias;
    return ext;
}

__device__ __forceinline__ int edge_at(const void* ei, int idx, int is64) {
    if (is64) return (int)((const long long*)ei)[idx];
    return ((const int*)ei)[idx];
}

// ---------------- init: zero deg/cur (all blocks) + dtype sniff (block 0) ---
__global__ void init_kernel(const void* ei) {
    int i = blockIdx.x * blockDim.x + threadIdx.x;
    if (i < NNODES) { g_deg[i] = 0; g_cur[i] = 0; }
    if (blockIdx.x == 0) {
        __shared__ int acc[256];
        int t = threadIdx.x;
        const unsigned* w = (const unsigned*)ei;
        unsigned o = 0;
        #pragma unroll
        for (int j = 0; j < 8; j++) o |= w[(t + j * 256) * 2 + 1];
        acc[t] = (int)(o != 0);
        __syncthreads();
        for (int s = 128; s > 0; s >>= 1) {
            if (t < s) acc[t] |= acc[t + s];
            __syncthreads();
        }
        if (t == 0) g_is64 = acc[0] ? 0 : 1;   // any nonzero odd word -> int32
    }
}

// ---------------- CSR build -------------------------------------------------
__global__ void count_kernel(const void* __restrict__ ei, int E) {
    int e = blockIdx.x * blockDim.x + threadIdx.x;
    if (e < E) atomicAdd(&g_deg[edge_at(ei, E + e, g_is64)], 1);
}

__global__ void scan_kernel(int n) {   // 1 block, 1024 threads, shuffle scan
    __shared__ int wsum[32];
    int t = threadIdx.x, lane = t & 31, w = t >> 5;
    const int chunk = 10;
    int base_i = t * chunk;
    int s = 0;
    #pragma unroll
    for (int i = 0; i < chunk; i++) {
        int idx = base_i + i;
        if (idx < n) s += g_deg[idx];
    }
    int v = s;
    #pragma unroll
    for (int o = 1; o < 32; o <<= 1) {
        int u = __shfl_up_sync(0xffffffffu, v, o);
        if (lane >= o) v += u;
    }
    if (lane == 31) wsum[w] = v;
    __syncthreads();
    if (w == 0) {
        int x = wsum[lane];
        #pragma unroll
        for (int o = 1; o < 32; o <<= 1) {
            int u = __shfl_up_sync(0xffffffffu, x, o);
            if (lane >= o) x += u;
        }
        wsum[lane] = x;
    }
    __syncthreads();
    int run = (w ? wsum[w - 1] : 0) + v - s;   // exclusive prefix
    #pragma unroll
    for (int i = 0; i < chunk; i++) {
        int idx = base_i + i;
        if (idx < n) { g_off[idx] = run; run += g_deg[idx]; }
    }
    if (t == 1023) g_off[n] = run;
}

__global__ void scatter_kernel(const void* __restrict__ ei, int E) {
    int e = blockIdx.x * blockDim.x + threadIdx.x;
    if (e < E) {
        int is64 = g_is64;
        int d = edge_at(ei, E + e, is64);
        int p = g_off[d] + atomicAdd(&g_cur[d], 1);
        g_csr[p] = edge_at(ei, e, is64);
    }
}

// ---------------- fused weight + bias build ---------------------------------
__global__ __launch_bounds__(128)
void build_b_kernel(const float* __restrict__ gat_w,
                    const float* __restrict__ res_w,
                    const float* __restrict__ att_src,
                    const float* __restrict__ att_dst,
                    const float* __restrict__ res_b)
{
    int r = blockIdx.x;
    int t = threadIdx.x;
    if (r < 512) {
        g_B[r * 128 + t] = gat_w[r * 128 + t];
        if (t == 0) g_bias[r] = 0.f;
    } else if (r < 1024) {
        g_B[r * 128 + t] = res_w[(r - 512) * 128 + t];
        if (t == 0) g_bias[r] = res_b[r - 512];
    } else {
        int h = (r - 1024) & 3;
        const float* att = (r < 1028) ? att_src : att_dst;
        float s = 0.f;
        for (int c = 0; c < 128; c++)
            s = fmaf(att[h * 128 + c], gat_w[(size_t)(h * 128 + c) * 128 + t], s);
        g_B[r * 128 + t] = s;
        if (t == 0) g_bias[r] = 0.f;
    }
}

// ---------------- GEMM: C[m,n] = sum_k A[m,k]*B[n,k] (+bias)(+relu) --------
// BM=128, BN=64, BK=16, 256 threads, double-buffered smem.
// Thread tile 8(m)x4(n); accumulators packed in PAIRS ALONG M so that the
// packed A operand comes straight out of an LDS.128 (no repacking movs);
// only the 4 broadcast B values get duplicated (alu-pipe, hidden).
__global__ __launch_bounds__(256)
void gemm_kernel(const float* __restrict__ Aext, int Asel,
                 const float* __restrict__ Bext, int Bsel,
                 const float* __restrict__ biasext, int bsel,
                 float* __restrict__ Cext, int Csel,
                 int M, int N, int K, int ldc, int relu)
{
    const float* A = sel_ptr(Aext, Asel);
    const float* B = sel_ptr(Bext, Bsel);
    const float* bias = sel_ptr(biasext, bsel);
    float* C = (Csel == 1) ? g_X0 : (Csel == 2) ? g_X1 : (Csel == 3) ? g_U : Cext;

    __shared__ float As[2][16][132];
    __shared__ float Bs[2][16][68];

    const int tid = threadIdx.x;
    const int bm = blockIdx.x * 128, bn = blockIdx.y * 64;
    const int tx = tid & 15, ty = tid >> 4;

    // A tile 128x16 = 512 float4, 2 per thread; B tile 64x16 = 256 float4, 1/thread
    const int am0 = tid >> 2;            // 0..63
    const int am1 = 64 + (tid >> 2);     // 64..127
    const int ak4 = tid & 3;
    const int bn0 = tid >> 2;
    const int bk4 = tid & 3;

    float4 pa0, pa1, pb;
    const int nt = K >> 4;

    {   // prologue (kt = 0)
        int gm0 = bm + am0, gm1 = bm + am1, gn = bn + bn0;
        pa0 = (gm0 < M) ? *(const float4*)(A + (size_t)gm0 * K + ak4 * 4) : make_float4(0, 0, 0, 0);
        pa1 = (gm1 < M) ? *(const float4*)(A + (size_t)gm1 * K + ak4 * 4) : make_float4(0, 0, 0, 0);
        pb  = (gn  < N) ? *(const float4*)(B + (size_t)gn  * K + bk4 * 4) : make_float4(0, 0, 0, 0);
        As[0][ak4 * 4 + 0][am0] = pa0.x; As[0][ak4 * 4 + 1][am0] = pa0.y;
        As[0][ak4 * 4 + 2][am0] = pa0.z; As[0][ak4 * 4 + 3][am0] = pa0.w;
        As[0][ak4 * 4 + 0][am1] = pa1.x; As[0][ak4 * 4 + 1][am1] = pa1.y;
        As[0][ak4 * 4 + 2][am1] = pa1.z; As[0][ak4 * 4 + 3][am1] = pa1.w;
        Bs[0][bk4 * 4 + 0][bn0] = pb.x;  Bs[0][bk4 * 4 + 1][bn0] = pb.y;
        Bs[0][bk4 * 4 + 2][bn0] = pb.z;  Bs[0][bk4 * 4 + 3][bn0] = pb.w;
    }
    __syncthreads();

    // acc[i2][j] = packed pair {C[m0+2*i2], C[m0+2*i2+1]} for column j
    unsigned long long acc[4][4];
    const unsigned long long z = pk2(0.f, 0.f);
    #pragma unroll
    for (int i = 0; i < 4; i++)
        #pragma unroll
        for (int j = 0; j < 4; j++) acc[i][j] = z;

    for (int t = 0; t < nt; t++) {
        int cur = t & 1;
        if (t + 1 < nt) {
            int kt = (t + 1) << 4;
            int gm0 = bm + am0, gm1 = bm + am1, gn = bn + bn0;
            pa0 = (gm0 < M) ? *(const float4*)(A + (size_t)gm0 * K + kt + ak4 * 4) : make_float4(0, 0, 0, 0);
            pa1 = (gm1 < M) ? *(const float4*)(A + (size_t)gm1 * K + kt + ak4 * 4) : make_float4(0, 0, 0, 0);
            pb  = (gn  < N) ? *(const float4*)(B + (size_t)gn  * K + kt + bk4 * 4) : make_float4(0, 0, 0, 0);
        }
        #pragma unroll
        for (int k = 0; k < 16; k++) {
            // packed A pairs straight from LDS.128 (m-contiguous, 16B aligned)
            ulonglong2 ap0 = *(const ulonglong2*)&As[cur][k][ty * 8];
            ulonglong2 ap1 = *(const ulonglong2*)&As[cur][k][ty * 8 + 4];
            float4 bv = *(const float4*)&Bs[cur][k][tx * 4];
            unsigned long long ad[4] = {ap0.x, ap0.y, ap1.x, ap1.y};
            unsigned long long bd[4] = {pk2(bv.x, bv.x), pk2(bv.y, bv.y),
                                        pk2(bv.z, bv.z), pk2(bv.w, bv.w)};
            #pragma unroll
            for (int i = 0; i < 4; i++) {
                fma2(acc[i][0], ad[i], bd[0]);
                fma2(acc[i][1], ad[i], bd[1]);
                fma2(acc[i][2], ad[i], bd[2]);
                fma2(acc[i][3], ad[i], bd[3]);
            }
        }
        if (t + 1 < nt) {
            int nxt = cur ^ 1;
            As[nxt][ak4 * 4 + 0][am0] = pa0.x; As[nxt][ak4 * 4 + 1][am0] = pa0.y;
            As[nxt][ak4 * 4 + 2][am0] = pa0.z; As[nxt][ak4 * 4 + 3][am0] = pa0.w;
            As[nxt][ak4 * 4 + 0][am1] = pa1.x; As[nxt][ak4 * 4 + 1][am1] = pa1.y;
            As[nxt][ak4 * 4 + 2][am1] = pa1.z; As[nxt][ak4 * 4 + 3][am1] = pa1.w;
            Bs[nxt][bk4 * 4 + 0][bn0] = pb.x;  Bs[nxt][bk4 * 4 + 1][bn0] = pb.y;
            Bs[nxt][bk4 * 4 + 2][bn0] = pb.z;  Bs[nxt][bk4 * 4 + 3][bn0] = pb.w;
            __syncthreads();
        }
    }

    #pragma unroll
    for (int i2 = 0; i2 < 4; i2++) {
        #pragma unroll
        for (int p = 0; p < 2; p++) {
            int gm = bm + ty * 8 + i2 * 2 + p;
            if (gm >= M) continue;
            #pragma unroll
            for (int j = 0; j < 4; j++) {
                float lo, hi;
                upk2(lo, hi, acc[i2][j]);
                float v = p ? hi : lo;
                int gn = bn + tx * 4 + j;
                if (gn >= N) continue;
                if (bias) v += bias[gn];
                if (relu) v = fmaxf(v, 0.f);
                C[(size_t)gm * ldc + gn] = v;
            }
        }
    }
}

// ---------------- GAT aggregation + fused GraphCON epilogue ----------------
__global__ __launch_bounds__(128)
void node_kernel(const float* __restrict__ gat_b, int out_sel)
{
    float* Xnew = (out_sel == 1) ? g_X0 : g_X1;
    const int d = blockIdx.x, t = threadIdx.x;
    const int h = t >> 5, lane = t & 31;

    const float* ud = g_U + (size_t)d * UC;
    const float adv = ud[1028 + h];
    const float ls = lrelu(ud[1024 + h] + adv);
    const int e0 = g_off[d], e1 = g_off[d + 1];

    // ---- warp-level max over incoming logits (+self) ----
    float mx = ls;
    for (int i = e0 + lane; i < e1; i += 32) {
        int s = g_csr[i];
        mx = fmaxf(mx, lrelu(g_U[(size_t)s * UC + 1024 + h] + adv));
    }
    #pragma unroll
    for (int o = 16; o > 0; o >>= 1)
        mx = fmaxf(mx, __shfl_xor_sync(0xffffffffu, mx, o));

    // ---- fused pass: unnormalized weighted aggregate + weight sum ----
    float ws = expf(ls - mx);
    float ssum = ws;
    float4 xd4 = ((const float4*)ud)[t];
    float4 acc = make_float4(ws * xd4.x, ws * xd4.y, ws * xd4.z, ws * xd4.w);

    int i = e0;
    for (; i + 2 <= e1; i += 2) {
        int s0 = g_csr[i], s1 = g_csr[i + 1];
        const float* u0 = g_U + (size_t)s0 * UC;
        const float* u1 = g_U + (size_t)s1 * UC;
        float a0 = u0[1024 + h], a1 = u1[1024 + h];
        float4 v0 = ((const float4*)u0)[t];
        float4 v1 = ((const float4*)u1)[t];
        float w0 = expf(lrelu(a0 + adv) - mx);
        float w1 = expf(lrelu(a1 + adv) - mx);
        acc.x = fmaf(w0, v0.x, acc.x); acc.y = fmaf(w0, v0.y, acc.y);
        acc.z = fmaf(w0, v0.z, acc.z); acc.w = fmaf(w0, v0.w, acc.w);
        acc.x = fmaf(w1, v1.x, acc.x); acc.y = fmaf(w1, v1.y, acc.y);
        acc.z = fmaf(w1, v1.z, acc.z); acc.w = fmaf(w1, v1.w, acc.w);
        ssum += w0 + w1;
    }
    if (i < e1) {
        int s0 = g_csr[i];
        const float* u0 = g_U + (size_t)s0 * UC;
        float w0 = expf(lrelu(u0[1024 + h] + adv) - mx);
        float4 v0 = ((const float4*)u0)[t];
        acc.x = fmaf(w0, v0.x, acc.x); acc.y = fmaf(w0, v0.y, acc.y);
        acc.z = fmaf(w0, v0.z, acc.z); acc.w = fmaf(w0, v0.w, acc.w);
        ssum += w0;
    }

    float rcp = 1.f / ssum;
    float4 gb = ((const float4*)gat_b)[t];
    float4 rs = ((const float4*)(ud + 512))[t];
    float z = 0.25f * (eluf(fmaf(acc.x, rcp, gb.x + rs.x)) +
                       eluf(fmaf(acc.y, rcp, gb.y + rs.y)) +
                       eluf(fmaf(acc.z, rcp, gb.z + rs.z)) +
                       eluf(fmaf(acc.w, rcp, gb.w + rs.w)));
    Xnew[(size_t)d * NHID + t] = z;
}

// ---------------- host ------------------------------------------------------
extern "C" void kernel_launch(void* const* d_in, const int* in_sizes, int n_in,
                              void* d_out, int out_size)
{
    const float* x       = (const float*)d_in[0];
    const void*  ei      = d_in[1];
    const float* enc_w   = (const float*)d_in[2];
    const float* enc_b   = (const float*)d_in[3];
    const float* res_w   = (const float*)d_in[4];
    const float* res_b   = (const float*)d_in[5];
    const float* gat_w   = (const float*)d_in[6];
    const float* att_src = (const float*)d_in[7];
    const float* att_dst = (const float*)d_in[8];
    const float* gat_b   = (const float*)d_in[9];
    const float* dec_w   = (const float*)d_in[10];
    const float* dec_b   = (const float*)d_in[11];
    int E = in_sizes[1] / 2;

    init_kernel<<<(NNODES + 255) / 256, 256>>>(ei);
    count_kernel<<<(E + 255) / 256, 256>>>(ei, E);
    scan_kernel<<<1, 1024>>>(NNODES);
    scatter_kernel<<<(E + 255) / 256, 256>>>(ei, E);

    build_b_kernel<<<NB, 128>>>(gat_w, res_w, att_src, att_dst, res_b);

    // encoder: X0 = relu(x @ enc_w^T + enc_b)
    gemm_kernel<<<dim3(79, 2), 256>>>(x, 0, enc_w, 0, enc_b, 0, nullptr, 1,
                                      NNODES, 128, 256, 128, 1);

    for (int layer = 0; layer < 2; layer++) {
        int in_sel  = (layer == 0) ? 1 : 2;
        int out_sel = (layer == 0) ? 2 : 1;
        gemm_kernel<<<dim3(79, 17), 256>>>(nullptr, in_sel, nullptr, 4,
                                           nullptr, 5, nullptr, 3,
                                           NNODES, NB, 128, UC, 0);
        node_kernel<<<NNODES, 128>>>(gat_b, out_sel);
    }

    // decoder
    gemm_kernel<<<dim3(79, 1), 256>>>(nullptr, 1, dec_w, 0, dec_b, 0,
                                      (float*)d_out, 0,
                                      NNODES, 40, 128, 40, 0);
}

// round 6
// speedup vs baseline: 1.4485x; 1.0882x over previous
#include <cuda_runtime.h>
#include <math.h>

#define NNODES 10000
#define NHID   128
#define UC     1032   // U row: xh(512) | res(512) | a_src(4) | a_dst(4)
#define NB     1032
#define EMAX   160000

// ---------------- scratch (device globals; no allocation allowed) ----------
__device__ float g_X0[NNODES * NHID];
__device__ float g_X1[NNODES * NHID];
__device__ float g_U [NNODES * UC];
__device__ float g_B [NB * NHID];     // fused weights [1032,128]
__device__ float g_bias[NB];
__device__ int   g_deg[NNODES];
__device__ int   g_cur[NNODES];
__device__ int   g_off[NNODES + 1];
__device__ int   g_csr[EMAX];
__device__ int   g_is64;

// ---------------- helpers ---------------------------------------------------
__device__ __forceinline__ float lrelu(float x) { return x > 0.f ? x : 0.2f * x; }
__device__ __forceinline__ float eluf (float x) { return x > 0.f ? x : (__expf(x) - 1.f); }

__device__ __forceinline__ unsigned long long pk2(float lo, float hi) {
    unsigned long long r;
    asm("mov.b64 %0, {%1, %2};" : "=l"(r) : "f"(lo), "f"(hi));
    return r;
}
__device__ __forceinline__ void fma2(unsigned long long& d,
                                     unsigned long long a, unsigned long long b) {
    asm("fma.rn.f32x2 %0, %1, %2, %3;" : "=l"(d) : "l"(a), "l"(b), "l"(d));
}
__device__ __forceinline__ void upk2(float& lo, float& hi, unsigned long long v) {
    asm("mov.b64 {%0, %1}, %2;" : "=f"(lo), "=f"(hi) : "l"(v));
}

__device__ __forceinline__ const float* sel_ptr(const float* ext, int sel) {
    if (sel == 1) return g_X0;
    if (sel == 2) return g_X1;
    if (sel == 3) return g_U;
    if (sel == 4) return g_B;
    if (sel == 5) return g_bias;
    return ext;
}

__device__ __forceinline__ int edge_at(const void* ei, int idx, int is64) {
    if (is64) return (int)((const long long*)ei)[idx];
    return ((const int*)ei)[idx];
}

// ---------------- init: zero deg/cur (all blocks) + dtype sniff (block 0) ---
__global__ void init_kernel(const void* ei) {
    int i = blockIdx.x * blockDim.x + threadIdx.x;
    if (i < NNODES) { g_deg[i] = 0; g_cur[i] = 0; }
    if (blockIdx.x == 0) {
        __shared__ int acc[256];
        int t = threadIdx.x;
        const unsigned* w = (const unsigned*)ei;
        unsigned o = 0;
        #pragma unroll
        for (int j = 0; j < 8; j++) o |= w[(t + j * 256) * 2 + 1];
        acc[t] = (int)(o != 0);
        __syncthreads();
        for (int s = 128; s > 0; s >>= 1) {
            if (t < s) acc[t] |= acc[t + s];
            __syncthreads();
        }
        if (t == 0) g_is64 = acc[0] ? 0 : 1;   // any nonzero odd word -> int32
    }
}

// ---------------- CSR build -------------------------------------------------
__global__ void count_kernel(const void* __restrict__ ei, int E) {
    int e = blockIdx.x * blockDim.x + threadIdx.x;
    if (e < E) atomicAdd(&g_deg[edge_at(ei, E + e, g_is64)], 1);
}

__global__ void scan_kernel(int n) {   // 1 block, 1024 threads, shuffle scan
    __shared__ int wsum[32];
    int t = threadIdx.x, lane = t & 31, w = t >> 5;
    const int chunk = 10;
    int base_i = t * chunk;
    int s = 0;
    #pragma unroll
    for (int i = 0; i < chunk; i++) {
        int idx = base_i + i;
        if (idx < n) s += g_deg[idx];
    }
    int v = s;
    #pragma unroll
    for (int o = 1; o < 32; o <<= 1) {
        int u = __shfl_up_sync(0xffffffffu, v, o);
        if (lane >= o) v += u;
    }
    if (lane == 31) wsum[w] = v;
    __syncthreads();
    if (w == 0) {
        int x = wsum[lane];
        #pragma unroll
        for (int o = 1; o < 32; o <<= 1) {
            int u = __shfl_up_sync(0xffffffffu, x, o);
            if (lane >= o) x += u;
        }
        wsum[lane] = x;
    }
    __syncthreads();
    int run = (w ? wsum[w - 1] : 0) + v - s;   // exclusive prefix
    #pragma unroll
    for (int i = 0; i < chunk; i++) {
        int idx = base_i + i;
        if (idx < n) { g_off[idx] = run; run += g_deg[idx]; }
    }
    if (t == 1023) g_off[n] = run;
}

__global__ void scatter_kernel(const void* __restrict__ ei, int E) {
    int e = blockIdx.x * blockDim.x + threadIdx.x;
    if (e < E) {
        int is64 = g_is64;
        int d = edge_at(ei, E + e, is64);
        int p = g_off[d] + atomicAdd(&g_cur[d], 1);
        g_csr[p] = edge_at(ei, e, is64);
    }
}

// ---------------- fused weight + bias build ---------------------------------
__global__ __launch_bounds__(128)
void build_b_kernel(const float* __restrict__ gat_w,
                    const float* __restrict__ res_w,
                    const float* __restrict__ att_src,
                    const float* __restrict__ att_dst,
                    const float* __restrict__ res_b)
{
    int r = blockIdx.x;
    int t = threadIdx.x;
    if (r < 512) {
        g_B[r * 128 + t] = gat_w[r * 128 + t];
        if (t == 0) g_bias[r] = 0.f;
    } else if (r < 1024) {
        g_B[r * 128 + t] = res_w[(r - 512) * 128 + t];
        if (t == 0) g_bias[r] = res_b[r - 512];
    } else {
        int h = (r - 1024) & 3;
        const float* att = (r < 1028) ? att_src : att_dst;
        float s = 0.f;
        for (int c = 0; c < 128; c++)
            s = fmaf(att[h * 128 + c], gat_w[(size_t)(h * 128 + c) * 128 + t], s);
        g_B[r * 128 + t] = s;
        if (t == 0) g_bias[r] = 0.f;
    }
}

// ---------------- GEMM: C[m,n] = sum_k A[m,k]*B[n,k] (+bias)(+relu) --------
// BM=128, BN=64, BK=16, 256 threads, double-buffered smem, f32x2 packed
// accumulators paired along M (packed A comes straight from LDS.128).
__global__ __launch_bounds__(256)
void gemm_kernel(const float* __restrict__ Aext, int Asel,
                 const float* __restrict__ Bext, int Bsel,
                 const float* __restrict__ biasext, int bsel,
                 float* __restrict__ Cext, int Csel,
                 int M, int N, int K, int ldc, int relu)
{
    const float* A = sel_ptr(Aext, Asel);
    const float* B = sel_ptr(Bext, Bsel);
    const float* bias = sel_ptr(biasext, bsel);
    float* C = (Csel == 1) ? g_X0 : (Csel == 2) ? g_X1 : (Csel == 3) ? g_U : Cext;

    __shared__ float As[2][16][132];
    __shared__ float Bs[2][16][68];

    const int tid = threadIdx.x;
    const int bm = blockIdx.x * 128, bn = blockIdx.y * 64;
    const int tx = tid & 15, ty = tid >> 4;

    const int am0 = tid >> 2;
    const int am1 = 64 + (tid >> 2);
    const int ak4 = tid & 3;
    const int bn0 = tid >> 2;
    const int bk4 = tid & 3;

    float4 pa0, pa1, pb;
    const int nt = K >> 4;

    {   // prologue (kt = 0)
        int gm0 = bm + am0, gm1 = bm + am1, gn = bn + bn0;
        pa0 = (gm0 < M) ? *(const float4*)(A + (size_t)gm0 * K + ak4 * 4) : make_float4(0, 0, 0, 0);
        pa1 = (gm1 < M) ? *(const float4*)(A + (size_t)gm1 * K + ak4 * 4) : make_float4(0, 0, 0, 0);
        pb  = (gn  < N) ? *(const float4*)(B + (size_t)gn  * K + bk4 * 4) : make_float4(0, 0, 0, 0);
        As[0][ak4 * 4 + 0][am0] = pa0.x; As[0][ak4 * 4 + 1][am0] = pa0.y;
        As[0][ak4 * 4 + 2][am0] = pa0.z; As[0][ak4 * 4 + 3][am0] = pa0.w;
        As[0][ak4 * 4 + 0][am1] = pa1.x; As[0][ak4 * 4 + 1][am1] = pa1.y;
        As[0][ak4 * 4 + 2][am1] = pa1.z; As[0][ak4 * 4 + 3][am1] = pa1.w;
        Bs[0][bk4 * 4 + 0][bn0] = pb.x;  Bs[0][bk4 * 4 + 1][bn0] = pb.y;
        Bs[0][bk4 * 4 + 2][bn0] = pb.z;  Bs[0][bk4 * 4 + 3][bn0] = pb.w;
    }
    __syncthreads();

    unsigned long long acc[4][4];
    const unsigned long long z = pk2(0.f, 0.f);
    #pragma unroll
    for (int i = 0; i < 4; i++)
        #pragma unroll
        for (int j = 0; j < 4; j++) acc[i][j] = z;

    for (int t = 0; t < nt; t++) {
        int cur = t & 1;
        if (t + 1 < nt) {
            int kt = (t + 1) << 4;
            int gm0 = bm + am0, gm1 = bm + am1, gn = bn + bn0;
            pa0 = (gm0 < M) ? *(const float4*)(A + (size_t)gm0 * K + kt + ak4 * 4) : make_float4(0, 0, 0, 0);
            pa1 = (gm1 < M) ? *(const float4*)(A + (size_t)gm1 * K + kt + ak4 * 4) : make_float4(0, 0, 0, 0);
            pb  = (gn  < N) ? *(const float4*)(B + (size_t)gn  * K + kt + bk4 * 4) : make_float4(0, 0, 0, 0);
        }
        #pragma unroll
        for (int k = 0; k < 16; k++) {
            ulonglong2 ap0 = *(const ulonglong2*)&As[cur][k][ty * 8];
            ulonglong2 ap1 = *(const ulonglong2*)&As[cur][k][ty * 8 + 4];
            float4 bv = *(const float4*)&Bs[cur][k][tx * 4];
            unsigned long long ad[4] = {ap0.x, ap0.y, ap1.x, ap1.y};
            unsigned long long bd[4] = {pk2(bv.x, bv.x), pk2(bv.y, bv.y),
                                        pk2(bv.z, bv.z), pk2(bv.w, bv.w)};
            #pragma unroll
            for (int i = 0; i < 4; i++) {
                fma2(acc[i][0], ad[i], bd[0]);
                fma2(acc[i][1], ad[i], bd[1]);
                fma2(acc[i][2], ad[i], bd[2]);
                fma2(acc[i][3], ad[i], bd[3]);
            }
        }
        if (t + 1 < nt) {
            int nxt = cur ^ 1;
            As[nxt][ak4 * 4 + 0][am0] = pa0.x; As[nxt][ak4 * 4 + 1][am0] = pa0.y;
            As[nxt][ak4 * 4 + 2][am0] = pa0.z; As[nxt][ak4 * 4 + 3][am0] = pa0.w;
            As[nxt][ak4 * 4 + 0][am1] = pa1.x; As[nxt][ak4 * 4 + 1][am1] = pa1.y;
            As[nxt][ak4 * 4 + 2][am1] = pa1.z; As[nxt][ak4 * 4 + 3][am1] = pa1.w;
            Bs[nxt][bk4 * 4 + 0][bn0] = pb.x;  Bs[nxt][bk4 * 4 + 1][bn0] = pb.y;
            Bs[nxt][bk4 * 4 + 2][bn0] = pb.z;  Bs[nxt][bk4 * 4 + 3][bn0] = pb.w;
            __syncthreads();
        }
    }

    #pragma unroll
    for (int i2 = 0; i2 < 4; i2++) {
        #pragma unroll
        for (int p = 0; p < 2; p++) {
            int gm = bm + ty * 8 + i2 * 2 + p;
            if (gm >= M) continue;
            #pragma unroll
            for (int j = 0; j < 4; j++) {
                float lo, hi;
                upk2(lo, hi, acc[i2][j]);
                float v = p ? hi : lo;
                int gn = bn + tx * 4 + j;
                if (gn >= N) continue;
                if (bias) v += bias[gn];
                if (relu) v = fmaxf(v, 0.f);
                C[(size_t)gm * ldc + gn] = v;
            }
        }
    }
}

// ---------------- GAT aggregation + fused GraphCON epilogue ----------------
// one block per destination node, 128 threads; thread t owns flat channels
// 4t..4t+3 (head h = t>>5). Single pass: softmax stabilized by the SELF
// logit (exact cancellation), per-edge weights computed ONCE into smem.
__global__ __launch_bounds__(128)
void node_kernel(const float* __restrict__ gat_b, int out_sel)
{
    float* Xnew = (out_sel == 1) ? g_X0 : g_X1;
    const int d = blockIdx.x, t = threadIdx.x;
    const int h = t >> 5;

    __shared__ float s_adv[4];   // a_dst[d, h]
    __shared__ float s_ls [4];   // self logit per head
    __shared__ float sw[128];    // 32 edges x 4 heads
    __shared__ int   si[32];

    const float* ud = g_U + (size_t)d * UC;
    if (t < 4) {
        float adv = ud[1028 + t];
        s_adv[t] = adv;
        s_ls[t]  = lrelu(ud[1024 + t] + adv);
    }
    __syncthreads();

    const int e0 = g_off[d], e1 = g_off[d + 1];

    // self contribution: weight = exp(ls - ls) = 1
    float ssum = 1.f;
    float4 xd4 = ((const float4*)ud)[t];
    float4 acc = xd4;

    const int jj = t >> 2, hh = t & 3;   // staging role: edge jj, head hh
    const float adv_h = s_adv[hh];
    const float ls_h  = s_ls[hh];

    for (int base = e0; base < e1; base += 32) {
        int cnt = min(32, e1 - base);
        if (jj < cnt) {
            int s = g_csr[base + jj];
            if (hh == 0) si[jj] = s;
            float as = g_U[(size_t)s * UC + 1024 + hh];
            sw[jj * 4 + hh] = __expf(lrelu(as + adv_h) - ls_h);
        }
        __syncthreads();

        int j = 0;
        for (; j + 2 <= cnt; j += 2) {
            int s0 = si[j], s1 = si[j + 1];
            float w0 = sw[j * 4 + h], w1 = sw[j * 4 + 4 + h];
            float4 v0 = ((const float4*)(g_U + (size_t)s0 * UC))[t];
            float4 v1 = ((const float4*)(g_U + (size_t)s1 * UC))[t];
            acc.x = fmaf(w0, v0.x, acc.x); acc.y = fmaf(w0, v0.y, acc.y);
            acc.z = fmaf(w0, v0.z, acc.z); acc.w = fmaf(w0, v0.w, acc.w);
            acc.x = fmaf(w1, v1.x, acc.x); acc.y = fmaf(w1, v1.y, acc.y);
            acc.z = fmaf(w1, v1.z, acc.z); acc.w = fmaf(w1, v1.w, acc.w);
            ssum += w0 + w1;
        }
        if (j < cnt) {
            int s0 = si[j];
            float w0 = sw[j * 4 + h];
            float4 v0 = ((const float4*)(g_U + (size_t)s0 * UC))[t];
            acc.x = fmaf(w0, v0.x, acc.x); acc.y = fmaf(w0, v0.y, acc.y);
            acc.z = fmaf(w0, v0.z, acc.z); acc.w = fmaf(w0, v0.w, acc.w);
            ssum += w0;
        }
        __syncthreads();
    }

    // epilogue: v = conv/ssum + gat_b + res; z = mean over the 4 flat elems
    float rcp = 1.f / ssum;
    float4 gb = ((const float4*)gat_b)[t];
    float4 rs = ((const float4*)(ud + 512))[t];
    float z = 0.25f * (eluf(fmaf(acc.x, rcp, gb.x + rs.x)) +
                       eluf(fmaf(acc.y, rcp, gb.y + rs.y)) +
                       eluf(fmaf(acc.z, rcp, gb.z + rs.z)) +
                       eluf(fmaf(acc.w, rcp, gb.w + rs.w)));
    Xnew[(size_t)d * NHID + t] = z;
}

// ---------------- host ------------------------------------------------------
extern "C" void kernel_launch(void* const* d_in, const int* in_sizes, int n_in,
                              void* d_out, int out_size)
{
    const float* x       = (const float*)d_in[0];
    const void*  ei      = d_in[1];
    const float* enc_w   = (const float*)d_in[2];
    const float* enc_b   = (const float*)d_in[3];
    const float* res_w   = (const float*)d_in[4];
    const float* res_b   = (const float*)d_in[5];
    const float* gat_w   = (const float*)d_in[6];
    const float* att_src = (const float*)d_in[7];
    const float* att_dst = (const float*)d_in[8];
    const float* gat_b   = (const float*)d_in[9];
    const float* dec_w   = (const float*)d_in[10];
    const float* dec_b   = (const float*)d_in[11];
    int E = in_sizes[1] / 2;

    init_kernel<<<(NNODES + 255) / 256, 256>>>(ei);
    count_kernel<<<(E + 255) / 256, 256>>>(ei, E);
    scan_kernel<<<1, 1024>>>(NNODES);
    scatter_kernel<<<(E + 255) / 256, 256>>>(ei, E);

    build_b_kernel<<<NB, 128>>>(gat_w, res_w, att_src, att_dst, res_b);

    // encoder: X0 = relu(x @ enc_w^T + enc_b)
    gemm_kernel<<<dim3(79, 2), 256>>>(x, 0, enc_w, 0, enc_b, 0, nullptr, 1,
                                      NNODES, 128, 256, 128, 1);

    for (int layer = 0; layer < 2; layer++) {
        int in_sel  = (layer == 0) ? 1 : 2;
        int out_sel = (layer == 0) ? 2 : 1;
        gemm_kernel<<<dim3(79, 17), 256>>>(nullptr, in_sel, nullptr, 4,
                                           nullptr, 5, nullptr, 3,
                                           NNODES, NB, 128, UC, 0);
        node_kernel<<<NNODES, 128>>>(gat_b, out_sel);
    }

    // decoder
    gemm_kernel<<<dim3(79, 1), 256>>>(nullptr, 1, dec_w, 0, dec_b, 0,
                                      (float*)d_out, 0,
                                      NNODES, 40, 128, 40, 0);
}